// round 15
// baseline (speedup 1.0000x reference)
#include <cuda_runtime.h>
#include <cuda_bf16.h>
#include <cuda_fp16.h>
#include <cstdint>

// ---------------------------------------------------------------------------
// BidirectionalMambaLayer — Round 15: DRAM-traffic reduction.
// Intermediates fp16 where precision allows: z (gate), delta, u-for-scan
// (reuses the fp16 u the x_proj GEMM already consumes). u_raw stays fp32 for
// the conv. GEMM core = round 12 (best known, 457us).
// ---------------------------------------------------------------------------

#define SEQL   1024
#define NB     2
#define MTOT   (NB * SEQL)
#define DMODEL 768
#define DINNER 1536
#define DSTATE 16
#define DTRANK 48
#define DCONV  4
#define XZW    (2 * DINNER)            // 3072
#define XDBLW  (DTRANK + 2 * DSTATE)   // 80

// -------------------------- scratch (device globals) -----------------------
__device__ float  g_uraw [2][(size_t)MTOT * DINNER];  // in_proj u half (fp32)
__device__ __half g_z    [2][(size_t)MTOT * DINNER];  // in_proj z half (fp16)
__device__ __half g_ur   [2][(size_t)MTOT * DINNER];  // conv+silu out (fp16)
__device__ float  g_xdbl [2][(size_t)MTOT * XDBLW];   // x_proj totals (fp32)
__device__ __half g_delta[2][(size_t)MTOT * DINNER];  // softplus (fp16)
__device__ __half g_ypre [2][(size_t)MTOT * DINNER];  // scan out (fp16)
__device__ __half g_xr   [(size_t)MTOT * DMODEL];     // fp16 x
__device__ __half g_win  [2][(size_t)XZW * DMODEL];
__device__ __half g_wxp  [2][(size_t)XDBLW * DINNER];
__device__ __half g_wdt  [2][(size_t)DINNER * DTRANK];
__device__ __half g_wout [2][(size_t)DMODEL * DINNER];

enum { HBUF_XR = 0, HBUF_UR, HBUF_YPRE,
       HBUF_WIN, HBUF_WXP, HBUF_WOUT };

__device__ __forceinline__ __half* scratch_h(int id, int dir) {
    switch (id) {
        case HBUF_XR:   return g_xr;
        case HBUF_UR:   return g_ur[dir];
        case HBUF_YPRE: return g_ypre[dir];
        case HBUF_WIN:  return g_win[dir];
        case HBUF_WXP:  return g_wxp[dir];
        case HBUF_WOUT: return g_wout[dir];
    }
    return nullptr;
}

__device__ __forceinline__ void cp16(uint32_t saddr, const __half* gptr, bool ok) {
    int sz = ok ? 16 : 0;
    asm volatile("cp.async.cg.shared.global [%0], [%1], 16, %2;"
                 :: "r"(saddr), "l"(gptr), "r"(sz));
}
__device__ __forceinline__ void cp_commit() { asm volatile("cp.async.commit_group;"); }
__device__ __forceinline__ void cp_wait1()  { asm volatile("cp.async.wait_group 1;"); }
__device__ __forceinline__ void cp_wait0()  { asm volatile("cp.async.wait_group 0;"); }

__device__ __forceinline__ void ldsm_x4(uint32_t& r0, uint32_t& r1,
                                        uint32_t& r2, uint32_t& r3, uint32_t a) {
    asm volatile("ldmatrix.sync.aligned.m8n8.x4.shared.b16 {%0,%1,%2,%3}, [%4];"
                 : "=r"(r0), "=r"(r1), "=r"(r2), "=r"(r3) : "r"(a));
}

#define MMA_F16(acc, a, b)                                              \
    asm volatile(                                                       \
        "mma.sync.aligned.m16n8k16.row.col.f32.f16.f16.f32 "            \
        "{%0,%1,%2,%3}, {%4,%5,%6,%7}, {%8,%9}, {%0,%1,%2,%3};"         \
        : "+f"((acc)[0]), "+f"((acc)[1]), "+f"((acc)[2]), "+f"((acc)[3])\
        : "r"((a)[0]), "r"((a)[1]), "r"((a)[2]), "r"((a)[3]),           \
          "r"((b)[0]), "r"((b)[1]))

// ---------------------------------------------------------------------------
// fp16 mma.sync TN GEMM (round-12 core): BM=BN=128, BK=64, STG=3 dyn smem,
// 8 warps (2m x 4n), warp tile 64x32, fragment double-buffer.
// OUTMODE: 0 = plain fp32 store, 1 = fp32 atomicAdd, 2 = in_proj split
// (n<DINNER -> g_uraw fp32; n>=DINNER -> g_z fp16).
// ---------------------------------------------------------------------------
#define GBK   64
#define GSTG  3
#define GSASX 72
#define SMEM_G (GSTG * (128 * GSASX * 2) * 2)   // 110592 B

template<bool FLIPA1, int OUTMODE>
__global__ __launch_bounds__(256)
void gemm_h(int aId, int bId,
            float* __restrict__ Cext, float* __restrict__ Cd0, float* __restrict__ Cd1,
            int N, int K, int lda, int ldc, int nxt, int kchunk)
{
    constexpr int CPR = GBK / 8;
    constexpr int LIT = 128 * CPR / 256;

    const int dir = blockIdx.z;
    const __half* A = scratch_h(aId, dir);
    const __half* W = scratch_h(bId, dir);
    float* C = Cext ? Cext : (dir ? Cd1 : Cd0);

    const int split = blockIdx.x / nxt;
    const int bn    = (blockIdx.x - split * nxt) * 128;
    const int bm    = blockIdx.y * 128;
    const int kbeg  = split * kchunk;
    const int T     = kchunk / GBK;

    extern __shared__ __half dynsmem_h[];

    const int tid  = threadIdx.x;
    const int lane = tid & 31;
    const int warp = tid >> 5;
    const int wm   = warp >> 2;
    const int wn   = warp & 3;
    const int gr   = lane >> 2;
    const int tq   = lane & 3;

    const uint32_t stage_bytes = 128 * GSASX * 2;
    const uint32_t sAb = (uint32_t)__cvta_generic_to_shared(dynsmem_h);
    const uint32_t sBb = sAb + GSTG * stage_bytes;

    const uint32_t laneA =
        ((uint32_t)((wm * 64 + (lane & 15)) * GSASX + (lane >> 4) * 8)) * 2;
    const uint32_t laneB =
        ((uint32_t)((wn * 32 + (lane & 7) + ((lane & 16) ? 8 : 0)) * GSASX +
                    ((lane & 8) ? 8 : 0))) * 2;

    int arow[LIT], aq[LIT];
    uint32_t soff[LIT];
#pragma unroll
    for (int i = 0; i < LIT; i++) {
        const int c = tid + i * 256;
        arow[i] = c / CPR;
        aq[i]   = (c - arow[i] * CPR) * 8;
        soff[i] = (uint32_t)(arow[i] * GSASX + aq[i]) * 2;
    }

    auto load_tile = [&](int t, int st) {
        const int kof = kbeg + t * GBK;
#pragma unroll
        for (int i = 0; i < LIT; i++) {
            int gm = bm + arow[i];
            if (FLIPA1 && dir) gm ^= (SEQL - 1);
            cp16(sAb + st * stage_bytes + soff[i],
                 A + (size_t)gm * lda + kof + aq[i], true);
        }
#pragma unroll
        for (int i = 0; i < LIT; i++) {
            const int wr = bn + arow[i];
            cp16(sBb + st * stage_bytes + soff[i],
                 W + (size_t)wr * K + kof + aq[i], wr < N);
        }
        cp_commit();
    };

    float acc[4][4][4];
#pragma unroll
    for (int mt = 0; mt < 4; mt++)
#pragma unroll
        for (int nt = 0; nt < 4; nt++)
#pragma unroll
            for (int r = 0; r < 4; r++) acc[mt][nt][r] = 0.f;

    load_tile(0, 0);
    if (T > 1) load_tile(1, 1);

    for (int t = 0; t < T; t++) {
        const int st  = t % GSTG;
        const int rem = T - 1 - t;
        if (rem >= 1) cp_wait1(); else cp_wait0();
        __syncthreads();

        if (t + 2 < T) load_tile(t + 2, (t + 2) % GSTG);

        const uint32_t aAddr = sAb + st * stage_bytes + laneA;
        const uint32_t bAddr = sBb + st * stage_bytes + laneB;

        uint32_t a[2][4][4], b[2][4][2];
#pragma unroll
        for (int mt = 0; mt < 4; mt++)
            ldsm_x4(a[0][mt][0], a[0][mt][1], a[0][mt][2], a[0][mt][3],
                    aAddr + (uint32_t)(mt * 16 * GSASX) * 2);
#pragma unroll
        for (int p = 0; p < 2; p++)
            ldsm_x4(b[0][2 * p][0], b[0][2 * p][1],
                    b[0][2 * p + 1][0], b[0][2 * p + 1][1],
                    bAddr + (uint32_t)(p * 16 * GSASX) * 2);

#pragma unroll
        for (int ks = 0; ks < GBK / 16; ks++) {
            const int cur = ks & 1;
            if (ks + 1 < GBK / 16) {
                const int nb = cur ^ 1;
                const uint32_t kb2 = (uint32_t)((ks + 1) * 16) * 2;
#pragma unroll
                for (int mt = 0; mt < 4; mt++)
                    ldsm_x4(a[nb][mt][0], a[nb][mt][1], a[nb][mt][2], a[nb][mt][3],
                            aAddr + (uint32_t)(mt * 16 * GSASX) * 2 + kb2);
#pragma unroll
                for (int p = 0; p < 2; p++)
                    ldsm_x4(b[nb][2 * p][0], b[nb][2 * p][1],
                            b[nb][2 * p + 1][0], b[nb][2 * p + 1][1],
                            bAddr + (uint32_t)(p * 16 * GSASX) * 2 + kb2);
            }
#pragma unroll
            for (int mt = 0; mt < 4; mt++)
#pragma unroll
                for (int nt = 0; nt < 4; nt++)
                    MMA_F16(acc[mt][nt], a[cur][mt], b[cur][nt]);
        }
    }

    // epilogue
    const bool zside = (OUTMODE == 2) && (bn >= DINNER);
    float*  up = (OUTMODE == 2) ? g_uraw[dir] : nullptr;
    __half* zp = (OUTMODE == 2) ? g_z[dir]    : nullptr;

#pragma unroll
    for (int mt = 0; mt < 4; mt++) {
        const int m0 = bm + wm * 64 + mt * 16 + gr;
#pragma unroll
        for (int half = 0; half < 2; half++) {
            const int m = m0 + half * 8;
#pragma unroll
            for (int nt = 0; nt < 4; nt++) {
                const int nbase = bn + wn * 32 + nt * 8 + 2 * tq;
#pragma unroll
                for (int j = 0; j < 2; j++) {
                    const int n = nbase + j;
                    if (n >= N) continue;
                    const float v = acc[mt][nt][half * 2 + j];
                    if (OUTMODE == 0) {
                        C[(size_t)m * ldc + n] = v;
                    } else if (OUTMODE == 1) {
                        atomicAdd(&C[(size_t)m * ldc + n], v);
                    } else {
                        if (zside) zp[(size_t)m * DINNER + (n - DINNER)] = __float2half_rn(v);
                        else       up[(size_t)m * DINNER + n] = v;
                    }
                }
            }
        }
    }
}

// ---------------------------------------------------------------------------
// Fused small-K delta GEMM: delta(fp16) = softplus(dt @ dt_w^T + dt_b), K=48.
// ---------------------------------------------------------------------------
#define DSASX 56
__global__ __launch_bounds__(256, 2)
void gemm_delta(const float* __restrict__ dt_b0, const float* __restrict__ dt_b1)
{
    const int dir = blockIdx.z;
    const float*  Xd = g_xdbl[dir];
    const __half* W  = g_wdt[dir];
    const float*  bias = dir ? dt_b1 : dt_b0;
    __half*       Cc = g_delta[dir];

    __shared__ __half sA[128 * DSASX];
    __shared__ __half sB[128 * DSASX];

    const int bn = blockIdx.x * 128;
    const int bm = blockIdx.y * 128;

    const int tid  = threadIdx.x;
    const int lane = tid & 31;
    const int warp = tid >> 5;
    const int wm   = warp >> 2;
    const int wn   = warp & 3;
    const int gr   = lane >> 2;
    const int tq   = lane & 3;

    const uint32_t sAb = (uint32_t)__cvta_generic_to_shared(sA);
    const uint32_t sBb = (uint32_t)__cvta_generic_to_shared(sB);

#pragma unroll
    for (int i = 0; i < 3; i++) {
        const int c = tid + i * 256;
        const int r = c / 6, q = (c - r * 6) * 8;
        cp16(sBb + (uint32_t)(r * DSASX + q) * 2, W + (size_t)(bn + r) * DTRANK + q, true);
    }
    cp_commit();

#pragma unroll
    for (int i = 0; i < 6; i++) {
        const int c = tid + i * 256;
        const int r = c / 12, q = (c - r * 12) * 4;
        const float4 v = *(const float4*)(Xd + (size_t)(bm + r) * XDBLW + q);
        __half2* d2 = reinterpret_cast<__half2*>(&sA[r * DSASX + q]);
        d2[0] = __floats2half2_rn(v.x, v.y);
        d2[1] = __floats2half2_rn(v.z, v.w);
    }
    cp_wait0();
    __syncthreads();

    const uint32_t laneA =
        ((uint32_t)((wm * 64 + (lane & 15)) * DSASX + (lane >> 4) * 8)) * 2;
    const uint32_t laneB =
        ((uint32_t)((wn * 32 + (lane & 7) + ((lane & 16) ? 8 : 0)) * DSASX +
                    ((lane & 8) ? 8 : 0))) * 2;

    float acc[4][4][4];
#pragma unroll
    for (int mt = 0; mt < 4; mt++)
#pragma unroll
        for (int nt = 0; nt < 4; nt++)
#pragma unroll
            for (int r = 0; r < 4; r++) acc[mt][nt][r] = 0.f;

#pragma unroll
    for (int ks = 0; ks < 3; ks++) {
        const uint32_t kb2 = (uint32_t)(ks * 16) * 2;
        uint32_t a[4][4], b[4][2];
#pragma unroll
        for (int mt = 0; mt < 4; mt++)
            ldsm_x4(a[mt][0], a[mt][1], a[mt][2], a[mt][3],
                    sAb + laneA + (uint32_t)(mt * 16 * DSASX) * 2 + kb2);
#pragma unroll
        for (int p = 0; p < 2; p++)
            ldsm_x4(b[2 * p][0], b[2 * p][1], b[2 * p + 1][0], b[2 * p + 1][1],
                    sBb + laneB + (uint32_t)(p * 16 * DSASX) * 2 + kb2);
#pragma unroll
        for (int mt = 0; mt < 4; mt++)
#pragma unroll
            for (int nt = 0; nt < 4; nt++)
                MMA_F16(acc[mt][nt], a[mt], b[nt]);
    }

#pragma unroll
    for (int mt = 0; mt < 4; mt++) {
        const int m0 = bm + wm * 64 + mt * 16 + gr;
#pragma unroll
        for (int half = 0; half < 2; half++) {
            const int m = m0 + half * 8;
#pragma unroll
            for (int nt = 0; nt < 4; nt++) {
                const int nbase = bn + wn * 32 + nt * 8 + 2 * tq;
#pragma unroll
                for (int j = 0; j < 2; j++) {
                    const int n = nbase + j;
                    float v = acc[mt][nt][half * 2 + j] + bias[n];
                    v = (v > 20.f) ? v : log1pf(__expf(v));
                    Cc[(size_t)m * DINNER + n] = __float2half_rn(v);
                }
            }
        }
    }
}

// ---------------------------------------------------------------------------
// Fused init: zero(out), zero(xdbl x2), + 9 fp16-conversion slices.
// ---------------------------------------------------------------------------
__global__ void init_kernel(float4* __restrict__ out4,
                            const float4* __restrict__ x,
                            const float4* __restrict__ fiw, const float4* __restrict__ biw,
                            const float4* __restrict__ fow, const float4* __restrict__ bow,
                            const float4* __restrict__ fxp, const float4* __restrict__ bxp,
                            const float4* __restrict__ fdw, const float4* __restrict__ bdw)
{
    const float4* src = nullptr; __half* hdst = nullptr; float4* zdst = nullptr; int n4;
    switch (blockIdx.y) {
        case 0:  zdst = out4;               n4 = MTOT * DMODEL / 4;    break;
        case 1:  zdst = (float4*)g_xdbl[0]; n4 = MTOT * XDBLW / 4;     break;
        case 2:  zdst = (float4*)g_xdbl[1]; n4 = MTOT * XDBLW / 4;     break;
        case 3:  src = x;   hdst = g_xr;      n4 = MTOT * DMODEL / 4;   break;
        case 4:  src = fiw; hdst = g_win[0];  n4 = XZW * DMODEL / 4;    break;
        case 5:  src = biw; hdst = g_win[1];  n4 = XZW * DMODEL / 4;    break;
        case 6:  src = fow; hdst = g_wout[0]; n4 = DMODEL * DINNER / 4; break;
        case 7:  src = bow; hdst = g_wout[1]; n4 = DMODEL * DINNER / 4; break;
        case 8:  src = fxp; hdst = g_wxp[0];  n4 = XDBLW * DINNER / 4;  break;
        case 9:  src = bxp; hdst = g_wxp[1];  n4 = XDBLW * DINNER / 4;  break;
        case 10: src = fdw; hdst = g_wdt[0];  n4 = DINNER * DTRANK / 4; break;
        default: src = bdw; hdst = g_wdt[1];  n4 = DINNER * DTRANK / 4; break;
    }
    if (src == nullptr) {
        for (int i = blockIdx.x * blockDim.x + threadIdx.x; i < n4;
             i += gridDim.x * blockDim.x)
            zdst[i] = make_float4(0.f, 0.f, 0.f, 0.f);
    } else {
        __half2* d2 = reinterpret_cast<__half2*>(hdst);
        for (int i = blockIdx.x * blockDim.x + threadIdx.x; i < n4;
             i += gridDim.x * blockDim.x) {
            float4 v = src[i];
            d2[2 * i + 0] = __floats2half2_rn(v.x, v.y);
            d2[2 * i + 1] = __floats2half2_rn(v.z, v.w);
        }
    }
}

// ---------------------------------------------------------------------------
// Causal depthwise conv (D_CONV=4) + bias + SiLU, l-tiled x4, reads g_uraw
// (fp32, dense stride DINNER), writes fp16 g_ur only.
// ---------------------------------------------------------------------------
__global__ void conv_silu_kernel(const float* __restrict__ f_conv_w,
                                 const float* __restrict__ f_conv_b,
                                 const float* __restrict__ b_conv_w,
                                 const float* __restrict__ b_conv_b)
{
    const int dir = blockIdx.y;
    const float* conv_w = dir ? b_conv_w : f_conv_w;
    const float* conv_b = dir ? b_conv_b : f_conv_b;

    const int NCH = DINNER / 4;
    const int idx = blockIdx.x * blockDim.x + threadIdx.x;
    if (idx >= (MTOT / 4) * NCH) return;
    const int rt   = idx / NCH;
    const int d4   = (idx - rt * NCH) * 4;
    const int row0 = rt * 4;
    const int l0   = row0 & (SEQL - 1);

    const float* ur = g_uraw[dir];
    float cw[4][4];
#pragma unroll
    for (int j = 0; j < 4; j++) {
        const float4 w = *(const float4*)(conv_w + (d4 + j) * DCONV);
        cw[j][0] = w.x; cw[j][1] = w.y; cw[j][2] = w.z; cw[j][3] = w.w;
    }

    float4 xv[7];
#pragma unroll
    for (int j = 0; j < 7; j++) {
        const int l = l0 - 3 + j;
        xv[j] = (l >= 0)
              ? *(const float4*)(ur + (size_t)(row0 - 3 + j) * DINNER + d4)
              : make_float4(0.f, 0.f, 0.f, 0.f);
    }
    const float4 bias = *(const float4*)(conv_b + d4);

#pragma unroll
    for (int i = 0; i < 4; i++) {
        float4 s = bias;
#pragma unroll
        for (int k = 0; k < 4; k++) {
            const float4 xvv = xv[i + k];
            s.x = fmaf(cw[0][k], xvv.x, s.x);
            s.y = fmaf(cw[1][k], xvv.y, s.y);
            s.z = fmaf(cw[2][k], xvv.z, s.z);
            s.w = fmaf(cw[3][k], xvv.w, s.w);
        }
        float4 o;
        o.x = s.x / (1.f + __expf(-s.x));
        o.y = s.y / (1.f + __expf(-s.y));
        o.z = s.z / (1.f + __expf(-s.z));
        o.w = s.w / (1.f + __expf(-s.w));
        __half2* h2 = reinterpret_cast<__half2*>(g_ur[dir] + (size_t)(row0 + i) * DINNER + d4);
        h2[0] = __floats2half2_rn(o.x, o.y);
        h2[1] = __floats2half2_rn(o.z, o.w);
    }
}

// ---------------------------------------------------------------------------
// Selective scan — unroll 8, group double-buffered. Reads fp16 delta/u/z,
// fp32 B/C. dir1 output pre-flipped, fp16.
// ---------------------------------------------------------------------------
#define UNR   8
#define NGRP  (SEQL / UNR)

__global__ __launch_bounds__(128)
void scan_kernel(const float* __restrict__ fAlog, const float* __restrict__ fD,
                 const float* __restrict__ bAlog, const float* __restrict__ bD)
{
    const int dir = blockIdx.y;
    const float* Alog = dir ? bAlog : fAlog;
    const float* Dp   = dir ? bD    : fD;
    const __half* delta = g_delta[dir];
    const __half* u     = g_ur[dir];
    const float*  xdbl  = g_xdbl[dir];
    const __half* zb    = g_z[dir];
    __half*       ypre  = g_ypre[dir];

    const int lane = threadIdx.x & 31;
    const int warp = threadIdx.x >> 5;
    const int half = lane >> 4;
    const int n    = lane & 15;

    const int c = blockIdx.x * 8 + warp * 2 + half;
    const int b = c / DINNER;
    const int d = c - b * DINNER;

    const float Aneg = -__expf(Alog[d * DSTATE + n]);
    const float Dd   = Dp[d];
    const bool  ln0  = (n == 0);

    const size_t rowbase = (size_t)b * SEQL;
    const __half* pDl = delta + rowbase * DINNER + d;
    const __half* pU  = u     + rowbase * DINNER + d;
    const float*  pB  = xdbl  + rowbase * XDBLW + DTRANK + n;
    const float*  pC  = pB + DSTATE;
    const __half* pZ  = zb    + rowbase * DINNER + d;

    float cdl[UNR], cuu[UNR], cBn[UNR], cCn[UNR], czz[UNR];

    auto load_grp = [&](int g, float* adl, float* auu, float* aBn,
                        float* aCn, float* azz) {
        const int l0 = g * UNR;
#pragma unroll
        for (int i = 0; i < UNR; i++) {
            adl[i] = __half2float(pDl[(size_t)(l0 + i) * DINNER]);
            auu[i] = __half2float(pU [(size_t)(l0 + i) * DINNER]);
            aBn[i] = pB[(size_t)(l0 + i) * XDBLW];
            aCn[i] = pC[(size_t)(l0 + i) * XDBLW];
        }
        if (ln0) {
#pragma unroll
            for (int i = 0; i < UNR; i++)
                azz[i] = __half2float(pZ[(size_t)(l0 + i) * DINNER]);
        }
    };

    load_grp(0, cdl, cuu, cBn, cCn, czz);
    float h = 0.f;

    for (int g = 0; g < NGRP; g++) {
        float ndl[UNR], nuu[UNR], nBn[UNR], nCn[UNR], nzz[UNR];
        load_grp((g + 1 < NGRP) ? (g + 1) : 0, ndl, nuu, nBn, nCn, nzz);

        float dA[UNR];
#pragma unroll
        for (int i = 0; i < UNR; i++) dA[i] = __expf(cdl[i] * Aneg);

        float yp[UNR];
#pragma unroll
        for (int i = 0; i < UNR; i++) {
            h = fmaf(dA[i], h, cdl[i] * cBn[i] * cuu[i]);
            yp[i] = h * cCn[i];
        }

#pragma unroll
        for (int s = 1; s <= 8; s <<= 1) {
#pragma unroll
            for (int i = 0; i < UNR; i++)
                yp[i] += __shfl_xor_sync(0xffffffffu, yp[i], s);
        }

        if (ln0) {
            const int l0 = g * UNR;
#pragma unroll
            for (int i = 0; i < UNR; i++) {
                float y = fmaf(cuu[i], Dd, yp[i]);
                const float zz = czz[i];
                y *= zz / (1.f + __expf(-zz));
                const size_t row  = rowbase + l0 + i;
                const size_t orow = dir ? (row ^ (SEQL - 1)) : row;
                ypre[orow * DINNER + d] = __float2half_rn(y);
            }
        }

#pragma unroll
        for (int i = 0; i < UNR; i++) {
            cdl[i] = ndl[i]; cuu[i] = nuu[i];
            cBn[i] = nBn[i]; cCn[i] = nCn[i]; czz[i] = nzz[i];
        }
    }
}

// ---------------------------------------------------------------------------
// Host launch.
// ---------------------------------------------------------------------------
extern "C" void kernel_launch(void* const* d_in, const int* in_sizes, int n_in,
                              void* d_out, int out_size)
{
    const float* x = (const float*)d_in[0];
    float* out = (float*)d_out;

    const float* f_in_w    = (const float*)d_in[1];
    const float* f_conv_w  = (const float*)d_in[2];
    const float* f_conv_b  = (const float*)d_in[3];
    const float* f_xproj_w = (const float*)d_in[4];
    const float* f_dt_w    = (const float*)d_in[5];
    const float* f_dt_b    = (const float*)d_in[6];
    const float* f_Alog    = (const float*)d_in[7];
    const float* f_D       = (const float*)d_in[8];
    const float* f_out_w   = (const float*)d_in[9];
    const float* b_in_w    = (const float*)d_in[10];
    const float* b_conv_w  = (const float*)d_in[11];
    const float* b_conv_b  = (const float*)d_in[12];
    const float* b_xproj_w = (const float*)d_in[13];
    const float* b_dt_w    = (const float*)d_in[14];
    const float* b_dt_b    = (const float*)d_in[15];
    const float* b_Alog    = (const float*)d_in[16];
    const float* b_D       = (const float*)d_in[17];
    const float* b_out_w   = (const float*)d_in[18];

    float* xdbl0; float* xdbl1;
    cudaGetSymbolAddress((void**)&xdbl0, g_xdbl);
    xdbl1 = xdbl0 + (size_t)MTOT * XDBLW;

    cudaFuncSetAttribute(gemm_h<true,  2>,
                         cudaFuncAttributeMaxDynamicSharedMemorySize, SMEM_G);
    cudaFuncSetAttribute(gemm_h<false, 1>,
                         cudaFuncAttributeMaxDynamicSharedMemorySize, SMEM_G);

    // fused init: zero out/xdbl + fp16 conversion of all GEMM operands
    init_kernel<<<dim3(160, 12), 256>>>(
        (float4*)out, (const float4*)x,
        (const float4*)f_in_w,    (const float4*)b_in_w,
        (const float4*)f_out_w,   (const float4*)b_out_w,
        (const float4*)f_xproj_w, (const float4*)b_xproj_w,
        (const float4*)f_dt_w,    (const float4*)b_dt_w);

    // in_proj: split output (u_raw fp32 | z fp16)   [2048,3072], K=768
    gemm_h<true, 2><<<dim3(XZW / 128, MTOT / 128, 2), 256, SMEM_G>>>(
        HBUF_XR, HBUF_WIN, nullptr, nullptr, nullptr,
        XZW, DMODEL, DMODEL, XZW, XZW / 128, DMODEL);

    // depthwise conv + SiLU (fp32 in, fp16 out)
    conv_silu_kernel<<<dim3(((MTOT / 4) * (DINNER / 4) + 255) / 256, 2), 256>>>(
        f_conv_w, f_conv_b, b_conv_w, b_conv_b);

    // x_proj (split-K x8, atomic): xdbl += u_h @ xproj_w^T   [2048,80], K=1536
    gemm_h<false, 1><<<dim3(8, MTOT / 128, 2), 256, SMEM_G>>>(
        HBUF_UR, HBUF_WXP, nullptr, xdbl0, xdbl1,
        XDBLW, DINNER, DINNER, XDBLW, 1, DINNER / 8);

    // delta (fp16 out): softplus(dt @ dt_w^T + dt_b)  [2048,1536], K=48
    gemm_delta<<<dim3(DINNER / 128, MTOT / 128, 2), 256>>>(f_dt_b, b_dt_b);

    // selective scan (fp16 inputs; dir1 output pre-flipped)
    scan_kernel<<<dim3((NB * DINNER) / 8, 2), 128>>>(f_Alog, f_D, b_Alog, b_D);

    // out_proj (split-K x2, atomic): out += ypre_h @ out_w^T  [2048,768], K=1536
    gemm_h<false, 1><<<dim3((DMODEL / 128) * 2, MTOT / 128, 2), 256, SMEM_G>>>(
        HBUF_YPRE, HBUF_WOUT, out, nullptr, nullptr,
        DMODEL, DINNER, DINNER, DMODEL, DMODEL / 128, DINNER / 2);
}

// round 16
// speedup vs baseline: 1.0603x; 1.0603x over previous
#include <cuda_runtime.h>
#include <cuda_bf16.h>
#include <cuda_fp16.h>
#include <cstdint>

// ---------------------------------------------------------------------------
// BidirectionalMambaLayer — Round 16: round-12 baseline (best known, 457us)
// + packed-fp16 xz (in_proj output), fp16-only conv output, scan reads fp16
// u/z. delta path and all GEMM mainloops unchanged.
// ---------------------------------------------------------------------------

#define SEQL   1024
#define NB     2
#define MTOT   (NB * SEQL)
#define DMODEL 768
#define DINNER 1536
#define DSTATE 16
#define DTRANK 48
#define DCONV  4
#define XZW    (2 * DINNER)            // 3072
#define XDBLW  (DTRANK + 2 * DSTATE)   // 80

// -------------------------- scratch (device globals) -----------------------
__device__ __half g_xzh  [2][(size_t)MTOT * XZW];     // in_proj out (fp16, u|z)
__device__ __half g_ur   [2][(size_t)MTOT * DINNER];  // conv+silu out (fp16)
__device__ float  g_xdbl [2][(size_t)MTOT * XDBLW];   // x_proj totals (fp32)
__device__ float  g_delta[2][(size_t)MTOT * DINNER];  // softplus (fp32)
__device__ __half g_ypre [2][(size_t)MTOT * DINNER];  // scan out (fp16)
__device__ __half g_xr   [(size_t)MTOT * DMODEL];     // fp16 x
__device__ __half g_win  [2][(size_t)XZW * DMODEL];
__device__ __half g_wxp  [2][(size_t)XDBLW * DINNER];
__device__ __half g_wdt  [2][(size_t)DINNER * DTRANK];
__device__ __half g_wout [2][(size_t)DMODEL * DINNER];

enum { HBUF_XR = 0, HBUF_UR, HBUF_YPRE,
       HBUF_WIN, HBUF_WXP, HBUF_WOUT };

__device__ __forceinline__ __half* scratch_h(int id, int dir) {
    switch (id) {
        case HBUF_XR:   return g_xr;
        case HBUF_UR:   return g_ur[dir];
        case HBUF_YPRE: return g_ypre[dir];
        case HBUF_WIN:  return g_win[dir];
        case HBUF_WXP:  return g_wxp[dir];
        case HBUF_WOUT: return g_wout[dir];
    }
    return nullptr;
}

__device__ __forceinline__ void cp16(uint32_t saddr, const __half* gptr, bool ok) {
    int sz = ok ? 16 : 0;
    asm volatile("cp.async.cg.shared.global [%0], [%1], 16, %2;"
                 :: "r"(saddr), "l"(gptr), "r"(sz));
}
__device__ __forceinline__ void cp_commit() { asm volatile("cp.async.commit_group;"); }
__device__ __forceinline__ void cp_wait1()  { asm volatile("cp.async.wait_group 1;"); }
__device__ __forceinline__ void cp_wait0()  { asm volatile("cp.async.wait_group 0;"); }

__device__ __forceinline__ void ldsm_x4(uint32_t& r0, uint32_t& r1,
                                        uint32_t& r2, uint32_t& r3, uint32_t a) {
    asm volatile("ldmatrix.sync.aligned.m8n8.x4.shared.b16 {%0,%1,%2,%3}, [%4];"
                 : "=r"(r0), "=r"(r1), "=r"(r2), "=r"(r3) : "r"(a));
}

#define MMA_F16(acc, a, b)                                              \
    asm volatile(                                                       \
        "mma.sync.aligned.m16n8k16.row.col.f32.f16.f16.f32 "            \
        "{%0,%1,%2,%3}, {%4,%5,%6,%7}, {%8,%9}, {%0,%1,%2,%3};"         \
        : "+f"((acc)[0]), "+f"((acc)[1]), "+f"((acc)[2]), "+f"((acc)[3])\
        : "r"((a)[0]), "r"((a)[1]), "r"((a)[2]), "r"((a)[3]),           \
          "r"((b)[0]), "r"((b)[1]))

// ---------------------------------------------------------------------------
// fp16 mma.sync TN GEMM (round-12 core): BM=BN=128, BK=64, STG=3 dyn smem,
// 8 warps (2m x 4n), warp tile 64x32, fragment double-buffer.
// OUTMODE: 0 = plain fp32 store, 1 = fp32 atomicAdd,
//          2 = packed __half2 store into Ch (single pointer, branch-free).
// ---------------------------------------------------------------------------
#define GBK   64
#define GSTG  3
#define GSASX 72
#define SMEM_G (GSTG * (128 * GSASX * 2) * 2)   // 110592 B

template<bool FLIPA1, int OUTMODE>
__global__ __launch_bounds__(256, 2)
void gemm_h(int aId, int bId,
            float* __restrict__ Cext, float* __restrict__ Cd0, float* __restrict__ Cd1,
            __half* __restrict__ Ch0, __half* __restrict__ Ch1,
            int N, int K, int lda, int ldc, int nxt, int kchunk)
{
    constexpr int CPR = GBK / 8;
    constexpr int LIT = 128 * CPR / 256;

    const int dir = blockIdx.z;
    const __half* A = scratch_h(aId, dir);
    const __half* W = scratch_h(bId, dir);
    float*  C  = Cext ? Cext : (dir ? Cd1 : Cd0);
    __half* Ch = dir ? Ch1 : Ch0;

    const int split = blockIdx.x / nxt;
    const int bn    = (blockIdx.x - split * nxt) * 128;
    const int bm    = blockIdx.y * 128;
    const int kbeg  = split * kchunk;
    const int T     = kchunk / GBK;

    extern __shared__ __half dynsmem_h[];

    const int tid  = threadIdx.x;
    const int lane = tid & 31;
    const int warp = tid >> 5;
    const int wm   = warp >> 2;
    const int wn   = warp & 3;
    const int gr   = lane >> 2;
    const int tq   = lane & 3;

    const uint32_t stage_bytes = 128 * GSASX * 2;
    const uint32_t sAb = (uint32_t)__cvta_generic_to_shared(dynsmem_h);
    const uint32_t sBb = sAb + GSTG * stage_bytes;

    const uint32_t laneA =
        ((uint32_t)((wm * 64 + (lane & 15)) * GSASX + (lane >> 4) * 8)) * 2;
    const uint32_t laneB =
        ((uint32_t)((wn * 32 + (lane & 7) + ((lane & 16) ? 8 : 0)) * GSASX +
                    ((lane & 8) ? 8 : 0))) * 2;

    int arow[LIT], aq[LIT];
    uint32_t soff[LIT];
#pragma unroll
    for (int i = 0; i < LIT; i++) {
        const int c = tid + i * 256;
        arow[i] = c / CPR;
        aq[i]   = (c - arow[i] * CPR) * 8;
        soff[i] = (uint32_t)(arow[i] * GSASX + aq[i]) * 2;
    }

    auto load_tile = [&](int t, int st) {
        const int kof = kbeg + t * GBK;
#pragma unroll
        for (int i = 0; i < LIT; i++) {
            int gm = bm + arow[i];
            if (FLIPA1 && dir) gm ^= (SEQL - 1);
            cp16(sAb + st * stage_bytes + soff[i],
                 A + (size_t)gm * lda + kof + aq[i], true);
        }
#pragma unroll
        for (int i = 0; i < LIT; i++) {
            const int wr = bn + arow[i];
            cp16(sBb + st * stage_bytes + soff[i],
                 W + (size_t)wr * K + kof + aq[i], wr < N);
        }
        cp_commit();
    };

    float acc[4][4][4];
#pragma unroll
    for (int mt = 0; mt < 4; mt++)
#pragma unroll
        for (int nt = 0; nt < 4; nt++)
#pragma unroll
            for (int r = 0; r < 4; r++) acc[mt][nt][r] = 0.f;

    load_tile(0, 0);
    if (T > 1) load_tile(1, 1);

    for (int t = 0; t < T; t++) {
        const int st  = t % GSTG;
        const int rem = T - 1 - t;
        if (rem >= 1) cp_wait1(); else cp_wait0();
        __syncthreads();

        if (t + 2 < T) load_tile(t + 2, (t + 2) % GSTG);

        const uint32_t aAddr = sAb + st * stage_bytes + laneA;
        const uint32_t bAddr = sBb + st * stage_bytes + laneB;

        uint32_t a[2][4][4], b[2][4][2];
#pragma unroll
        for (int mt = 0; mt < 4; mt++)
            ldsm_x4(a[0][mt][0], a[0][mt][1], a[0][mt][2], a[0][mt][3],
                    aAddr + (uint32_t)(mt * 16 * GSASX) * 2);
#pragma unroll
        for (int p = 0; p < 2; p++)
            ldsm_x4(b[0][2 * p][0], b[0][2 * p][1],
                    b[0][2 * p + 1][0], b[0][2 * p + 1][1],
                    bAddr + (uint32_t)(p * 16 * GSASX) * 2);

#pragma unroll
        for (int ks = 0; ks < GBK / 16; ks++) {
            const int cur = ks & 1;
            if (ks + 1 < GBK / 16) {
                const int nb = cur ^ 1;
                const uint32_t kb2 = (uint32_t)((ks + 1) * 16) * 2;
#pragma unroll
                for (int mt = 0; mt < 4; mt++)
                    ldsm_x4(a[nb][mt][0], a[nb][mt][1], a[nb][mt][2], a[nb][mt][3],
                            aAddr + (uint32_t)(mt * 16 * GSASX) * 2 + kb2);
#pragma unroll
                for (int p = 0; p < 2; p++)
                    ldsm_x4(b[nb][2 * p][0], b[nb][2 * p][1],
                            b[nb][2 * p + 1][0], b[nb][2 * p + 1][1],
                            bAddr + (uint32_t)(p * 16 * GSASX) * 2 + kb2);
            }
#pragma unroll
            for (int mt = 0; mt < 4; mt++)
#pragma unroll
                for (int nt = 0; nt < 4; nt++)
                    MMA_F16(acc[mt][nt], a[cur][mt], b[cur][nt]);
        }
    }

    // epilogue
#pragma unroll
    for (int mt = 0; mt < 4; mt++) {
        const int m0 = bm + wm * 64 + mt * 16 + gr;
#pragma unroll
        for (int half = 0; half < 2; half++) {
            const int m = m0 + half * 8;
#pragma unroll
            for (int nt = 0; nt < 4; nt++) {
                const int nb2 = bn + wn * 32 + nt * 8 + 2 * tq;
                if (OUTMODE == 2) {
                    // packed fp16 store (pair always in-bounds: N % 8 == 0)
                    if (nb2 < N) {
                        const __half2 hv = __floats2half2_rn(
                            acc[mt][nt][half * 2 + 0], acc[mt][nt][half * 2 + 1]);
                        *(__half2*)(Ch + (size_t)m * ldc + nb2) = hv;
                    }
                } else {
#pragma unroll
                    for (int j = 0; j < 2; j++) {
                        const int n = nb2 + j;
                        if (n < N) {
                            const float v = acc[mt][nt][half * 2 + j];
                            if (OUTMODE == 1) atomicAdd(&C[(size_t)m * ldc + n], v);
                            else              C[(size_t)m * ldc + n] = v;
                        }
                    }
                }
            }
        }
    }
}

// ---------------------------------------------------------------------------
// Fused small-K delta GEMM (unchanged, fp32 out):
// delta = softplus(dt @ dt_w^T + dt_b), K=48.
// ---------------------------------------------------------------------------
#define DSASX 56
__global__ __launch_bounds__(256, 2)
void gemm_delta(const float* __restrict__ dt_b0, const float* __restrict__ dt_b1)
{
    const int dir = blockIdx.z;
    const float*  Xd = g_xdbl[dir];
    const __half* W  = g_wdt[dir];
    const float*  bias = dir ? dt_b1 : dt_b0;
    float*        Cc = g_delta[dir];

    __shared__ __half sA[128 * DSASX];
    __shared__ __half sB[128 * DSASX];

    const int bn = blockIdx.x * 128;
    const int bm = blockIdx.y * 128;

    const int tid  = threadIdx.x;
    const int lane = tid & 31;
    const int warp = tid >> 5;
    const int wm   = warp >> 2;
    const int wn   = warp & 3;
    const int gr   = lane >> 2;
    const int tq   = lane & 3;

    const uint32_t sAb = (uint32_t)__cvta_generic_to_shared(sA);
    const uint32_t sBb = (uint32_t)__cvta_generic_to_shared(sB);

#pragma unroll
    for (int i = 0; i < 3; i++) {
        const int c = tid + i * 256;
        const int r = c / 6, q = (c - r * 6) * 8;
        cp16(sBb + (uint32_t)(r * DSASX + q) * 2, W + (size_t)(bn + r) * DTRANK + q, true);
    }
    cp_commit();

#pragma unroll
    for (int i = 0; i < 6; i++) {
        const int c = tid + i * 256;
        const int r = c / 12, q = (c - r * 12) * 4;
        const float4 v = *(const float4*)(Xd + (size_t)(bm + r) * XDBLW + q);
        __half2* d2 = reinterpret_cast<__half2*>(&sA[r * DSASX + q]);
        d2[0] = __floats2half2_rn(v.x, v.y);
        d2[1] = __floats2half2_rn(v.z, v.w);
    }
    cp_wait0();
    __syncthreads();

    const uint32_t laneA =
        ((uint32_t)((wm * 64 + (lane & 15)) * DSASX + (lane >> 4) * 8)) * 2;
    const uint32_t laneB =
        ((uint32_t)((wn * 32 + (lane & 7) + ((lane & 16) ? 8 : 0)) * DSASX +
                    ((lane & 8) ? 8 : 0))) * 2;

    float acc[4][4][4];
#pragma unroll
    for (int mt = 0; mt < 4; mt++)
#pragma unroll
        for (int nt = 0; nt < 4; nt++)
#pragma unroll
            for (int r = 0; r < 4; r++) acc[mt][nt][r] = 0.f;

#pragma unroll
    for (int ks = 0; ks < 3; ks++) {
        const uint32_t kb2 = (uint32_t)(ks * 16) * 2;
        uint32_t a[4][4], b[4][2];
#pragma unroll
        for (int mt = 0; mt < 4; mt++)
            ldsm_x4(a[mt][0], a[mt][1], a[mt][2], a[mt][3],
                    sAb + laneA + (uint32_t)(mt * 16 * DSASX) * 2 + kb2);
#pragma unroll
        for (int p = 0; p < 2; p++)
            ldsm_x4(b[2 * p][0], b[2 * p][1], b[2 * p + 1][0], b[2 * p + 1][1],
                    sBb + laneB + (uint32_t)(p * 16 * DSASX) * 2 + kb2);
#pragma unroll
        for (int mt = 0; mt < 4; mt++)
#pragma unroll
            for (int nt = 0; nt < 4; nt++)
                MMA_F16(acc[mt][nt], a[mt], b[nt]);
    }

#pragma unroll
    for (int mt = 0; mt < 4; mt++) {
        const int m0 = bm + wm * 64 + mt * 16 + gr;
#pragma unroll
        for (int half = 0; half < 2; half++) {
            const int m = m0 + half * 8;
#pragma unroll
            for (int nt = 0; nt < 4; nt++) {
                const int nbase = bn + wn * 32 + nt * 8 + 2 * tq;
#pragma unroll
                for (int j = 0; j < 2; j++) {
                    const int n = nbase + j;
                    float v = acc[mt][nt][half * 2 + j] + bias[n];
                    v = (v > 20.f) ? v : log1pf(__expf(v));
                    Cc[(size_t)m * DINNER + n] = v;
                }
            }
        }
    }
}

// ---------------------------------------------------------------------------
// Fused init: zero(out), zero(xdbl x2), + 9 fp16-conversion slices.
// ---------------------------------------------------------------------------
__global__ void init_kernel(float4* __restrict__ out4,
                            const float4* __restrict__ x,
                            const float4* __restrict__ fiw, const float4* __restrict__ biw,
                            const float4* __restrict__ fow, const float4* __restrict__ bow,
                            const float4* __restrict__ fxp, const float4* __restrict__ bxp,
                            const float4* __restrict__ fdw, const float4* __restrict__ bdw)
{
    const float4* src = nullptr; __half* hdst = nullptr; float4* zdst = nullptr; int n4;
    switch (blockIdx.y) {
        case 0:  zdst = out4;               n4 = MTOT * DMODEL / 4;    break;
        case 1:  zdst = (float4*)g_xdbl[0]; n4 = MTOT * XDBLW / 4;     break;
        case 2:  zdst = (float4*)g_xdbl[1]; n4 = MTOT * XDBLW / 4;     break;
        case 3:  src = x;   hdst = g_xr;      n4 = MTOT * DMODEL / 4;   break;
        case 4:  src = fiw; hdst = g_win[0];  n4 = XZW * DMODEL / 4;    break;
        case 5:  src = biw; hdst = g_win[1];  n4 = XZW * DMODEL / 4;    break;
        case 6:  src = fow; hdst = g_wout[0]; n4 = DMODEL * DINNER / 4; break;
        case 7:  src = bow; hdst = g_wout[1]; n4 = DMODEL * DINNER / 4; break;
        case 8:  src = fxp; hdst = g_wxp[0];  n4 = XDBLW * DINNER / 4;  break;
        case 9:  src = bxp; hdst = g_wxp[1];  n4 = XDBLW * DINNER / 4;  break;
        case 10: src = fdw; hdst = g_wdt[0];  n4 = DINNER * DTRANK / 4; break;
        default: src = bdw; hdst = g_wdt[1];  n4 = DINNER * DTRANK / 4; break;
    }
    if (src == nullptr) {
        for (int i = blockIdx.x * blockDim.x + threadIdx.x; i < n4;
             i += gridDim.x * blockDim.x)
            zdst[i] = make_float4(0.f, 0.f, 0.f, 0.f);
    } else {
        __half2* d2 = reinterpret_cast<__half2*>(hdst);
        for (int i = blockIdx.x * blockDim.x + threadIdx.x; i < n4;
             i += gridDim.x * blockDim.x) {
            float4 v = src[i];
            d2[2 * i + 0] = __floats2half2_rn(v.x, v.y);
            d2[2 * i + 1] = __floats2half2_rn(v.z, v.w);
        }
    }
}

// ---------------------------------------------------------------------------
// Causal depthwise conv (D_CONV=4) + bias + SiLU, l-tiled x4.
// Reads fp16 xz (u half), writes fp16 g_ur.
// ---------------------------------------------------------------------------
__global__ void conv_silu_kernel(const float* __restrict__ f_conv_w,
                                 const float* __restrict__ f_conv_b,
                                 const float* __restrict__ b_conv_w,
                                 const float* __restrict__ b_conv_b)
{
    const int dir = blockIdx.y;
    const float* conv_w = dir ? b_conv_w : f_conv_w;
    const float* conv_b = dir ? b_conv_b : f_conv_b;

    const int NCH = DINNER / 4;
    const int idx = blockIdx.x * blockDim.x + threadIdx.x;
    if (idx >= (MTOT / 4) * NCH) return;
    const int rt   = idx / NCH;
    const int d4   = (idx - rt * NCH) * 4;
    const int row0 = rt * 4;
    const int l0   = row0 & (SEQL - 1);

    const __half* xz = g_xzh[dir];
    float cw[4][4];
#pragma unroll
    for (int j = 0; j < 4; j++) {
        const float4 w = *(const float4*)(conv_w + (d4 + j) * DCONV);
        cw[j][0] = w.x; cw[j][1] = w.y; cw[j][2] = w.z; cw[j][3] = w.w;
    }

    float4 xv[7];
#pragma unroll
    for (int j = 0; j < 7; j++) {
        const int l = l0 - 3 + j;
        if (l >= 0) {
            const __half2* p = (const __half2*)(xz + (size_t)(row0 - 3 + j) * XZW + d4);
            const __half2 h0 = p[0], h1 = p[1];
            xv[j] = make_float4(__low2float(h0), __high2float(h0),
                                __low2float(h1), __high2float(h1));
        } else {
            xv[j] = make_float4(0.f, 0.f, 0.f, 0.f);
        }
    }
    const float4 bias = *(const float4*)(conv_b + d4);

#pragma unroll
    for (int i = 0; i < 4; i++) {
        float4 s = bias;
#pragma unroll
        for (int k = 0; k < 4; k++) {
            const float4 xvv = xv[i + k];
            s.x = fmaf(cw[0][k], xvv.x, s.x);
            s.y = fmaf(cw[1][k], xvv.y, s.y);
            s.z = fmaf(cw[2][k], xvv.z, s.z);
            s.w = fmaf(cw[3][k], xvv.w, s.w);
        }
        float4 o;
        o.x = s.x / (1.f + __expf(-s.x));
        o.y = s.y / (1.f + __expf(-s.y));
        o.z = s.z / (1.f + __expf(-s.z));
        o.w = s.w / (1.f + __expf(-s.w));
        __half2* h2 = reinterpret_cast<__half2*>(g_ur[dir] + (size_t)(row0 + i) * DINNER + d4);
        h2[0] = __floats2half2_rn(o.x, o.y);
        h2[1] = __floats2half2_rn(o.z, o.w);
    }
}

// ---------------------------------------------------------------------------
// Selective scan — unroll 8, group double-buffered. delta fp32; u/z fp16.
// dir1 output pre-flipped, fp16.
// ---------------------------------------------------------------------------
#define UNR   8
#define NGRP  (SEQL / UNR)

__global__ __launch_bounds__(128)
void scan_kernel(const float* __restrict__ fAlog, const float* __restrict__ fD,
                 const float* __restrict__ bAlog, const float* __restrict__ bD)
{
    const int dir = blockIdx.y;
    const float* Alog = dir ? bAlog : fAlog;
    const float* Dp   = dir ? bD    : fD;
    const float*  delta = g_delta[dir];
    const __half* u     = g_ur[dir];
    const float*  xdbl  = g_xdbl[dir];
    const __half* xz    = g_xzh[dir];
    __half*       ypre  = g_ypre[dir];

    const int lane = threadIdx.x & 31;
    const int warp = threadIdx.x >> 5;
    const int half = lane >> 4;
    const int n    = lane & 15;

    const int c = blockIdx.x * 8 + warp * 2 + half;
    const int b = c / DINNER;
    const int d = c - b * DINNER;

    const float Aneg = -__expf(Alog[d * DSTATE + n]);
    const float Dd   = Dp[d];
    const bool  ln0  = (n == 0);

    const size_t rowbase = (size_t)b * SEQL;
    const float*  pDl = delta + rowbase * DINNER + d;
    const __half* pU  = u     + rowbase * DINNER + d;
    const float*  pB  = xdbl  + rowbase * XDBLW + DTRANK + n;
    const float*  pC  = pB + DSTATE;
    const __half* pZ  = xz    + rowbase * XZW + DINNER + d;

    float cdl[UNR], cuu[UNR], cBn[UNR], cCn[UNR], czz[UNR];

    auto load_grp = [&](int g, float* adl, float* auu, float* aBn,
                        float* aCn, float* azz) {
        const int l0 = g * UNR;
#pragma unroll
        for (int i = 0; i < UNR; i++) {
            adl[i] = pDl[(size_t)(l0 + i) * DINNER];
            auu[i] = __half2float(pU[(size_t)(l0 + i) * DINNER]);
            aBn[i] = pB[(size_t)(l0 + i) * XDBLW];
            aCn[i] = pC[(size_t)(l0 + i) * XDBLW];
        }
        if (ln0) {
#pragma unroll
            for (int i = 0; i < UNR; i++)
                azz[i] = __half2float(pZ[(size_t)(l0 + i) * XZW]);
        }
    };

    load_grp(0, cdl, cuu, cBn, cCn, czz);
    float h = 0.f;

    for (int g = 0; g < NGRP; g++) {
        float ndl[UNR], nuu[UNR], nBn[UNR], nCn[UNR], nzz[UNR];
        load_grp((g + 1 < NGRP) ? (g + 1) : 0, ndl, nuu, nBn, nCn, nzz);

        float dA[UNR];
#pragma unroll
        for (int i = 0; i < UNR; i++) dA[i] = __expf(cdl[i] * Aneg);

        float yp[UNR];
#pragma unroll
        for (int i = 0; i < UNR; i++) {
            h = fmaf(dA[i], h, cdl[i] * cBn[i] * cuu[i]);
            yp[i] = h * cCn[i];
        }

#pragma unroll
        for (int s = 1; s <= 8; s <<= 1) {
#pragma unroll
            for (int i = 0; i < UNR; i++)
                yp[i] += __shfl_xor_sync(0xffffffffu, yp[i], s);
        }

        if (ln0) {
            const int l0 = g * UNR;
#pragma unroll
            for (int i = 0; i < UNR; i++) {
                float y = fmaf(cuu[i], Dd, yp[i]);
                const float zz = czz[i];
                y *= zz / (1.f + __expf(-zz));
                const size_t row  = rowbase + l0 + i;
                const size_t orow = dir ? (row ^ (SEQL - 1)) : row;
                ypre[orow * DINNER + d] = __float2half_rn(y);
            }
        }

#pragma unroll
        for (int i = 0; i < UNR; i++) {
            cdl[i] = ndl[i]; cuu[i] = nuu[i];
            cBn[i] = nBn[i]; cCn[i] = nCn[i]; czz[i] = nzz[i];
        }
    }
}

// ---------------------------------------------------------------------------
// Host launch.
// ---------------------------------------------------------------------------
extern "C" void kernel_launch(void* const* d_in, const int* in_sizes, int n_in,
                              void* d_out, int out_size)
{
    const float* x = (const float*)d_in[0];
    float* out = (float*)d_out;

    const float* f_in_w    = (const float*)d_in[1];
    const float* f_conv_w  = (const float*)d_in[2];
    const float* f_conv_b  = (const float*)d_in[3];
    const float* f_xproj_w = (const float*)d_in[4];
    const float* f_dt_w    = (const float*)d_in[5];
    const float* f_dt_b    = (const float*)d_in[6];
    const float* f_Alog    = (const float*)d_in[7];
    const float* f_D       = (const float*)d_in[8];
    const float* f_out_w   = (const float*)d_in[9];
    const float* b_in_w    = (const float*)d_in[10];
    const float* b_conv_w  = (const float*)d_in[11];
    const float* b_conv_b  = (const float*)d_in[12];
    const float* b_xproj_w = (const float*)d_in[13];
    const float* b_dt_w    = (const float*)d_in[14];
    const float* b_dt_b    = (const float*)d_in[15];
    const float* b_Alog    = (const float*)d_in[16];
    const float* b_D       = (const float*)d_in[17];
    const float* b_out_w   = (const float*)d_in[18];

    // device-global targets
    float* xdbl0; float* xdbl1;
    __half* xzh0; __half* xzh1;
    cudaGetSymbolAddress((void**)&xdbl0, g_xdbl);
    xdbl1 = xdbl0 + (size_t)MTOT * XDBLW;
    cudaGetSymbolAddress((void**)&xzh0, g_xzh);
    xzh1 = xzh0 + (size_t)MTOT * XZW;

    cudaFuncSetAttribute(gemm_h<true,  2>,
                         cudaFuncAttributeMaxDynamicSharedMemorySize, SMEM_G);
    cudaFuncSetAttribute(gemm_h<false, 1>,
                         cudaFuncAttributeMaxDynamicSharedMemorySize, SMEM_G);

    // fused init: zero out/xdbl + fp16 conversion of all GEMM operands
    init_kernel<<<dim3(160, 12), 256>>>(
        (float4*)out, (const float4*)x,
        (const float4*)f_in_w,    (const float4*)b_in_w,
        (const float4*)f_out_w,   (const float4*)b_out_w,
        (const float4*)f_xproj_w, (const float4*)b_xproj_w,
        (const float4*)f_dt_w,    (const float4*)b_dt_w);

    // in_proj (fp16 packed out): xz = x(flip dir1) @ in_w^T  [2048,3072], K=768
    gemm_h<true, 2><<<dim3(XZW / 128, MTOT / 128, 2), 256, SMEM_G>>>(
        HBUF_XR, HBUF_WIN, nullptr, nullptr, nullptr, xzh0, xzh1,
        XZW, DMODEL, DMODEL, XZW, XZW / 128, DMODEL);

    // depthwise conv + SiLU (fp16 in, fp16 out)
    conv_silu_kernel<<<dim3(((MTOT / 4) * (DINNER / 4) + 255) / 256, 2), 256>>>(
        f_conv_w, f_conv_b, b_conv_w, b_conv_b);

    // x_proj (split-K x8, atomic): xdbl += u_h @ xproj_w^T   [2048,80], K=1536
    gemm_h<false, 1><<<dim3(8, MTOT / 128, 2), 256, SMEM_G>>>(
        HBUF_UR, HBUF_WXP, nullptr, xdbl0, xdbl1, nullptr, nullptr,
        XDBLW, DINNER, DINNER, XDBLW, 1, DINNER / 8);

    // delta (fp32 out): softplus(dt @ dt_w^T + dt_b)  [2048,1536], K=48
    gemm_delta<<<dim3(DINNER / 128, MTOT / 128, 2), 256>>>(f_dt_b, b_dt_b);

    // selective scan (delta fp32, u/z fp16; dir1 output pre-flipped)
    scan_kernel<<<dim3((NB * DINNER) / 8, 2), 128>>>(f_Alog, f_D, b_Alog, b_D);

    // out_proj (split-K x2, atomic): out += ypre_h @ out_w^T  [2048,768], K=1536
    gemm_h<false, 1><<<dim3((DMODEL / 128) * 2, MTOT / 128, 2), 256, SMEM_G>>>(
        HBUF_YPRE, HBUF_WOUT, out, nullptr, nullptr, nullptr, nullptr,
        DMODEL, DINNER, DINNER, DMODEL, DMODEL / 128, DINNER / 2);
}

// round 17
// speedup vs baseline: 1.1400x; 1.0752x over previous
#include <cuda_runtime.h>
#include <cuda_bf16.h>
#include <cuda_fp16.h>
#include <cstdint>

// ---------------------------------------------------------------------------
// BidirectionalMambaLayer — Round 17: round-12 GEMMs (best known) + isolated
// traffic cuts: fp32 u buffer deleted (scan reads the fp16 u that x_proj
// uses), delta stored fp16. in_proj path byte-identical to round 12.
// ---------------------------------------------------------------------------

#define SEQL   1024
#define NB     2
#define MTOT   (NB * SEQL)
#define DMODEL 768
#define DINNER 1536
#define DSTATE 16
#define DTRANK 48
#define DCONV  4
#define XZW    (2 * DINNER)            // 3072
#define XDBLW  (DTRANK + 2 * DSTATE)   // 80

// -------------------------- scratch (device globals) -----------------------
__device__ float  g_xz   [2][(size_t)MTOT * XZW];     // in_proj out (fp32)
__device__ __half g_ur   [2][(size_t)MTOT * DINNER];  // conv+silu out (fp16)
__device__ float  g_xdbl [2][(size_t)MTOT * XDBLW];   // x_proj totals (fp32)
__device__ __half g_delta[2][(size_t)MTOT * DINNER];  // softplus (fp16)
__device__ __half g_ypre [2][(size_t)MTOT * DINNER];  // scan out (fp16)
__device__ __half g_xr   [(size_t)MTOT * DMODEL];     // fp16 x
__device__ __half g_win  [2][(size_t)XZW * DMODEL];
__device__ __half g_wxp  [2][(size_t)XDBLW * DINNER];
__device__ __half g_wdt  [2][(size_t)DINNER * DTRANK];
__device__ __half g_wout [2][(size_t)DMODEL * DINNER];

enum { HBUF_XR = 0, HBUF_UR, HBUF_YPRE,
       HBUF_WIN, HBUF_WXP, HBUF_WOUT };

__device__ __forceinline__ __half* scratch_h(int id, int dir) {
    switch (id) {
        case HBUF_XR:   return g_xr;
        case HBUF_UR:   return g_ur[dir];
        case HBUF_YPRE: return g_ypre[dir];
        case HBUF_WIN:  return g_win[dir];
        case HBUF_WXP:  return g_wxp[dir];
        case HBUF_WOUT: return g_wout[dir];
    }
    return nullptr;
}

__device__ __forceinline__ void cp16(uint32_t saddr, const __half* gptr, bool ok) {
    int sz = ok ? 16 : 0;
    asm volatile("cp.async.cg.shared.global [%0], [%1], 16, %2;"
                 :: "r"(saddr), "l"(gptr), "r"(sz));
}
__device__ __forceinline__ void cp_commit() { asm volatile("cp.async.commit_group;"); }
__device__ __forceinline__ void cp_wait1()  { asm volatile("cp.async.wait_group 1;"); }
__device__ __forceinline__ void cp_wait0()  { asm volatile("cp.async.wait_group 0;"); }

__device__ __forceinline__ void ldsm_x4(uint32_t& r0, uint32_t& r1,
                                        uint32_t& r2, uint32_t& r3, uint32_t a) {
    asm volatile("ldmatrix.sync.aligned.m8n8.x4.shared.b16 {%0,%1,%2,%3}, [%4];"
                 : "=r"(r0), "=r"(r1), "=r"(r2), "=r"(r3) : "r"(a));
}

#define MMA_F16(acc, a, b)                                              \
    asm volatile(                                                       \
        "mma.sync.aligned.m16n8k16.row.col.f32.f16.f16.f32 "            \
        "{%0,%1,%2,%3}, {%4,%5,%6,%7}, {%8,%9}, {%0,%1,%2,%3};"         \
        : "+f"((acc)[0]), "+f"((acc)[1]), "+f"((acc)[2]), "+f"((acc)[3])\
        : "r"((a)[0]), "r"((a)[1]), "r"((a)[2]), "r"((a)[3]),           \
          "r"((b)[0]), "r"((b)[1]))

// ---------------------------------------------------------------------------
// fp16 mma.sync TN GEMM — byte-identical to round 12.
// BM=BN=128, BK=64, STG=3 dyn smem, 8 warps (2m x 4n), warp tile 64x32,
// fragment double-buffer, register-unclamped.
// ---------------------------------------------------------------------------
#define GBK   64
#define GSTG  3
#define GSASX 72
#define SMEM_G (GSTG * (128 * GSASX * 2) * 2)   // 110592 B

template<bool FLIPA1, bool ATOMIC>
__global__ __launch_bounds__(256)
void gemm_h(int aId, int bId,
            float* __restrict__ Cext, float* __restrict__ Cd0, float* __restrict__ Cd1,
            int N, int K, int lda, int ldc, int nxt, int kchunk)
{
    constexpr int CPR = GBK / 8;
    constexpr int LIT = 128 * CPR / 256;

    const int dir = blockIdx.z;
    const __half* A = scratch_h(aId, dir);
    const __half* W = scratch_h(bId, dir);
    float*        C = Cext ? Cext : (dir ? Cd1 : Cd0);

    const int split = blockIdx.x / nxt;
    const int bn    = (blockIdx.x - split * nxt) * 128;
    const int bm    = blockIdx.y * 128;
    const int kbeg  = split * kchunk;
    const int T     = kchunk / GBK;

    extern __shared__ __half dynsmem_h[];

    const int tid  = threadIdx.x;
    const int lane = tid & 31;
    const int warp = tid >> 5;
    const int wm   = warp >> 2;
    const int wn   = warp & 3;
    const int gr   = lane >> 2;
    const int tq   = lane & 3;

    const uint32_t stage_bytes = 128 * GSASX * 2;
    const uint32_t sAb = (uint32_t)__cvta_generic_to_shared(dynsmem_h);
    const uint32_t sBb = sAb + GSTG * stage_bytes;

    const uint32_t laneA =
        ((uint32_t)((wm * 64 + (lane & 15)) * GSASX + (lane >> 4) * 8)) * 2;
    const uint32_t laneB =
        ((uint32_t)((wn * 32 + (lane & 7) + ((lane & 16) ? 8 : 0)) * GSASX +
                    ((lane & 8) ? 8 : 0))) * 2;

    int arow[LIT], aq[LIT];
    uint32_t soff[LIT];
#pragma unroll
    for (int i = 0; i < LIT; i++) {
        const int c = tid + i * 256;
        arow[i] = c / CPR;
        aq[i]   = (c - arow[i] * CPR) * 8;
        soff[i] = (uint32_t)(arow[i] * GSASX + aq[i]) * 2;
    }

    auto load_tile = [&](int t, int st) {
        const int kof = kbeg + t * GBK;
#pragma unroll
        for (int i = 0; i < LIT; i++) {
            int gm = bm + arow[i];
            if (FLIPA1 && dir) gm ^= (SEQL - 1);
            cp16(sAb + st * stage_bytes + soff[i],
                 A + (size_t)gm * lda + kof + aq[i], true);
        }
#pragma unroll
        for (int i = 0; i < LIT; i++) {
            const int wr = bn + arow[i];
            cp16(sBb + st * stage_bytes + soff[i],
                 W + (size_t)wr * K + kof + aq[i], wr < N);
        }
        cp_commit();
    };

    float acc[4][4][4];
#pragma unroll
    for (int mt = 0; mt < 4; mt++)
#pragma unroll
        for (int nt = 0; nt < 4; nt++)
#pragma unroll
            for (int r = 0; r < 4; r++) acc[mt][nt][r] = 0.f;

    load_tile(0, 0);
    if (T > 1) load_tile(1, 1);

    for (int t = 0; t < T; t++) {
        const int st  = t % GSTG;
        const int rem = T - 1 - t;
        if (rem >= 1) cp_wait1(); else cp_wait0();
        __syncthreads();

        if (t + 2 < T) load_tile(t + 2, (t + 2) % GSTG);

        const uint32_t aAddr = sAb + st * stage_bytes + laneA;
        const uint32_t bAddr = sBb + st * stage_bytes + laneB;

        uint32_t a[2][4][4], b[2][4][2];
#pragma unroll
        for (int mt = 0; mt < 4; mt++)
            ldsm_x4(a[0][mt][0], a[0][mt][1], a[0][mt][2], a[0][mt][3],
                    aAddr + (uint32_t)(mt * 16 * GSASX) * 2);
#pragma unroll
        for (int p = 0; p < 2; p++)
            ldsm_x4(b[0][2 * p][0], b[0][2 * p][1],
                    b[0][2 * p + 1][0], b[0][2 * p + 1][1],
                    bAddr + (uint32_t)(p * 16 * GSASX) * 2);

#pragma unroll
        for (int ks = 0; ks < GBK / 16; ks++) {
            const int cur = ks & 1;
            if (ks + 1 < GBK / 16) {
                const int nb = cur ^ 1;
                const uint32_t kb2 = (uint32_t)((ks + 1) * 16) * 2;
#pragma unroll
                for (int mt = 0; mt < 4; mt++)
                    ldsm_x4(a[nb][mt][0], a[nb][mt][1], a[nb][mt][2], a[nb][mt][3],
                            aAddr + (uint32_t)(mt * 16 * GSASX) * 2 + kb2);
#pragma unroll
                for (int p = 0; p < 2; p++)
                    ldsm_x4(b[nb][2 * p][0], b[nb][2 * p][1],
                            b[nb][2 * p + 1][0], b[nb][2 * p + 1][1],
                            bAddr + (uint32_t)(p * 16 * GSASX) * 2 + kb2);
            }
#pragma unroll
            for (int mt = 0; mt < 4; mt++)
#pragma unroll
                for (int nt = 0; nt < 4; nt++)
                    MMA_F16(acc[mt][nt], a[cur][mt], b[cur][nt]);
        }
    }

    // epilogue (fp32)
#pragma unroll
    for (int mt = 0; mt < 4; mt++) {
        const int m0 = bm + wm * 64 + mt * 16 + gr;
#pragma unroll
        for (int half = 0; half < 2; half++) {
            const int m = m0 + half * 8;
#pragma unroll
            for (int nt = 0; nt < 4; nt++) {
                const int nbase = bn + wn * 32 + nt * 8 + 2 * tq;
#pragma unroll
                for (int j = 0; j < 2; j++) {
                    const int n = nbase + j;
                    if (n < N) {
                        const float v = acc[mt][nt][half * 2 + j];
                        if (ATOMIC) atomicAdd(&C[(size_t)m * ldc + n], v);
                        else        C[(size_t)m * ldc + n] = v;
                    }
                }
            }
        }
    }
}

// ---------------------------------------------------------------------------
// Fused small-K delta GEMM: delta(fp16) = softplus(dt @ dt_w^T + dt_b), K=48.
// ---------------------------------------------------------------------------
#define DSASX 56
__global__ __launch_bounds__(256, 2)
void gemm_delta(const float* __restrict__ dt_b0, const float* __restrict__ dt_b1)
{
    const int dir = blockIdx.z;
    const float*  Xd = g_xdbl[dir];
    const __half* W  = g_wdt[dir];
    const float*  bias = dir ? dt_b1 : dt_b0;
    __half*       Cc = g_delta[dir];

    __shared__ __half sA[128 * DSASX];
    __shared__ __half sB[128 * DSASX];

    const int bn = blockIdx.x * 128;
    const int bm = blockIdx.y * 128;

    const int tid  = threadIdx.x;
    const int lane = tid & 31;
    const int warp = tid >> 5;
    const int wm   = warp >> 2;
    const int wn   = warp & 3;
    const int gr   = lane >> 2;
    const int tq   = lane & 3;

    const uint32_t sAb = (uint32_t)__cvta_generic_to_shared(sA);
    const uint32_t sBb = (uint32_t)__cvta_generic_to_shared(sB);

#pragma unroll
    for (int i = 0; i < 3; i++) {
        const int c = tid + i * 256;
        const int r = c / 6, q = (c - r * 6) * 8;
        cp16(sBb + (uint32_t)(r * DSASX + q) * 2, W + (size_t)(bn + r) * DTRANK + q, true);
    }
    cp_commit();

#pragma unroll
    for (int i = 0; i < 6; i++) {
        const int c = tid + i * 256;
        const int r = c / 12, q = (c - r * 12) * 4;
        const float4 v = *(const float4*)(Xd + (size_t)(bm + r) * XDBLW + q);
        __half2* d2 = reinterpret_cast<__half2*>(&sA[r * DSASX + q]);
        d2[0] = __floats2half2_rn(v.x, v.y);
        d2[1] = __floats2half2_rn(v.z, v.w);
    }
    cp_wait0();
    __syncthreads();

    const uint32_t laneA =
        ((uint32_t)((wm * 64 + (lane & 15)) * DSASX + (lane >> 4) * 8)) * 2;
    const uint32_t laneB =
        ((uint32_t)((wn * 32 + (lane & 7) + ((lane & 16) ? 8 : 0)) * DSASX +
                    ((lane & 8) ? 8 : 0))) * 2;

    float acc[4][4][4];
#pragma unroll
    for (int mt = 0; mt < 4; mt++)
#pragma unroll
        for (int nt = 0; nt < 4; nt++)
#pragma unroll
            for (int r = 0; r < 4; r++) acc[mt][nt][r] = 0.f;

#pragma unroll
    for (int ks = 0; ks < 3; ks++) {
        const uint32_t kb2 = (uint32_t)(ks * 16) * 2;
        uint32_t a[4][4], b[4][2];
#pragma unroll
        for (int mt = 0; mt < 4; mt++)
            ldsm_x4(a[mt][0], a[mt][1], a[mt][2], a[mt][3],
                    sAb + laneA + (uint32_t)(mt * 16 * DSASX) * 2 + kb2);
#pragma unroll
        for (int p = 0; p < 2; p++)
            ldsm_x4(b[2 * p][0], b[2 * p][1], b[2 * p + 1][0], b[2 * p + 1][1],
                    sBb + laneB + (uint32_t)(p * 16 * DSASX) * 2 + kb2);
#pragma unroll
        for (int mt = 0; mt < 4; mt++)
#pragma unroll
            for (int nt = 0; nt < 4; nt++)
                MMA_F16(acc[mt][nt], a[mt], b[nt]);
    }

#pragma unroll
    for (int mt = 0; mt < 4; mt++) {
        const int m0 = bm + wm * 64 + mt * 16 + gr;
#pragma unroll
        for (int half = 0; half < 2; half++) {
            const int m = m0 + half * 8;
#pragma unroll
            for (int nt = 0; nt < 4; nt++) {
                const int nbase = bn + wn * 32 + nt * 8 + 2 * tq;
#pragma unroll
                for (int j = 0; j < 2; j++) {
                    const int n = nbase + j;
                    float v = acc[mt][nt][half * 2 + j] + bias[n];
                    v = (v > 20.f) ? v : log1pf(__expf(v));
                    Cc[(size_t)m * DINNER + n] = __float2half_rn(v);
                }
            }
        }
    }
}

// ---------------------------------------------------------------------------
// Fused init: zero(out), zero(xdbl x2), + 9 fp16-conversion slices.
// ---------------------------------------------------------------------------
__global__ void init_kernel(float4* __restrict__ out4,
                            const float4* __restrict__ x,
                            const float4* __restrict__ fiw, const float4* __restrict__ biw,
                            const float4* __restrict__ fow, const float4* __restrict__ bow,
                            const float4* __restrict__ fxp, const float4* __restrict__ bxp,
                            const float4* __restrict__ fdw, const float4* __restrict__ bdw)
{
    const float4* src = nullptr; __half* hdst = nullptr; float4* zdst = nullptr; int n4;
    switch (blockIdx.y) {
        case 0:  zdst = out4;               n4 = MTOT * DMODEL / 4;    break;
        case 1:  zdst = (float4*)g_xdbl[0]; n4 = MTOT * XDBLW / 4;     break;
        case 2:  zdst = (float4*)g_xdbl[1]; n4 = MTOT * XDBLW / 4;     break;
        case 3:  src = x;   hdst = g_xr;      n4 = MTOT * DMODEL / 4;   break;
        case 4:  src = fiw; hdst = g_win[0];  n4 = XZW * DMODEL / 4;    break;
        case 5:  src = biw; hdst = g_win[1];  n4 = XZW * DMODEL / 4;    break;
        case 6:  src = fow; hdst = g_wout[0]; n4 = DMODEL * DINNER / 4; break;
        case 7:  src = bow; hdst = g_wout[1]; n4 = DMODEL * DINNER / 4; break;
        case 8:  src = fxp; hdst = g_wxp[0];  n4 = XDBLW * DINNER / 4;  break;
        case 9:  src = bxp; hdst = g_wxp[1];  n4 = XDBLW * DINNER / 4;  break;
        case 10: src = fdw; hdst = g_wdt[0];  n4 = DINNER * DTRANK / 4; break;
        default: src = bdw; hdst = g_wdt[1];  n4 = DINNER * DTRANK / 4; break;
    }
    if (src == nullptr) {
        for (int i = blockIdx.x * blockDim.x + threadIdx.x; i < n4;
             i += gridDim.x * blockDim.x)
            zdst[i] = make_float4(0.f, 0.f, 0.f, 0.f);
    } else {
        __half2* d2 = reinterpret_cast<__half2*>(hdst);
        for (int i = blockIdx.x * blockDim.x + threadIdx.x; i < n4;
             i += gridDim.x * blockDim.x) {
            float4 v = src[i];
            d2[2 * i + 0] = __floats2half2_rn(v.x, v.y);
            d2[2 * i + 1] = __floats2half2_rn(v.z, v.w);
        }
    }
}

// ---------------------------------------------------------------------------
// Causal depthwise conv (D_CONV=4) + bias + SiLU, l-tiled x4.
// Reads fp32 g_xz (u half); writes fp16 g_ur only.
// ---------------------------------------------------------------------------
__global__ void conv_silu_kernel(const float* __restrict__ f_conv_w,
                                 const float* __restrict__ f_conv_b,
                                 const float* __restrict__ b_conv_w,
                                 const float* __restrict__ b_conv_b)
{
    const int dir = blockIdx.y;
    const float* conv_w = dir ? b_conv_w : f_conv_w;
    const float* conv_b = dir ? b_conv_b : f_conv_b;

    const int NCH = DINNER / 4;
    const int idx = blockIdx.x * blockDim.x + threadIdx.x;
    if (idx >= (MTOT / 4) * NCH) return;
    const int rt   = idx / NCH;
    const int d4   = (idx - rt * NCH) * 4;
    const int row0 = rt * 4;
    const int l0   = row0 & (SEQL - 1);

    const float* xz = g_xz[dir];
    float cw[4][4];
#pragma unroll
    for (int j = 0; j < 4; j++) {
        const float4 w = *(const float4*)(conv_w + (d4 + j) * DCONV);
        cw[j][0] = w.x; cw[j][1] = w.y; cw[j][2] = w.z; cw[j][3] = w.w;
    }

    float4 xv[7];
#pragma unroll
    for (int j = 0; j < 7; j++) {
        const int l = l0 - 3 + j;
        xv[j] = (l >= 0)
              ? *(const float4*)(xz + (size_t)(row0 - 3 + j) * XZW + d4)
              : make_float4(0.f, 0.f, 0.f, 0.f);
    }
    const float4 bias = *(const float4*)(conv_b + d4);

#pragma unroll
    for (int i = 0; i < 4; i++) {
        float4 s = bias;
#pragma unroll
        for (int k = 0; k < 4; k++) {
            const float4 xvv = xv[i + k];
            s.x = fmaf(cw[0][k], xvv.x, s.x);
            s.y = fmaf(cw[1][k], xvv.y, s.y);
            s.z = fmaf(cw[2][k], xvv.z, s.z);
            s.w = fmaf(cw[3][k], xvv.w, s.w);
        }
        float4 o;
        o.x = s.x / (1.f + __expf(-s.x));
        o.y = s.y / (1.f + __expf(-s.y));
        o.z = s.z / (1.f + __expf(-s.z));
        o.w = s.w / (1.f + __expf(-s.w));
        __half2* h2 = reinterpret_cast<__half2*>(g_ur[dir] + (size_t)(row0 + i) * DINNER + d4);
        h2[0] = __floats2half2_rn(o.x, o.y);
        h2[1] = __floats2half2_rn(o.z, o.w);
    }
}

// ---------------------------------------------------------------------------
// Selective scan — unroll 8, group double-buffered. delta/u fp16; z/B/C fp32.
// dir1 output pre-flipped, fp16.
// ---------------------------------------------------------------------------
#define UNR   8
#define NGRP  (SEQL / UNR)

__global__ __launch_bounds__(128)
void scan_kernel(const float* __restrict__ fAlog, const float* __restrict__ fD,
                 const float* __restrict__ bAlog, const float* __restrict__ bD)
{
    const int dir = blockIdx.y;
    const float* Alog = dir ? bAlog : fAlog;
    const float* Dp   = dir ? bD    : fD;
    const __half* delta = g_delta[dir];
    const __half* u     = g_ur[dir];
    const float*  xdbl  = g_xdbl[dir];
    const float*  xz    = g_xz[dir];
    __half*       ypre  = g_ypre[dir];

    const int lane = threadIdx.x & 31;
    const int warp = threadIdx.x >> 5;
    const int half = lane >> 4;
    const int n    = lane & 15;

    const int c = blockIdx.x * 8 + warp * 2 + half;
    const int b = c / DINNER;
    const int d = c - b * DINNER;

    const float Aneg = -__expf(Alog[d * DSTATE + n]);
    const float Dd   = Dp[d];
    const bool  ln0  = (n == 0);

    const size_t rowbase = (size_t)b * SEQL;
    const __half* pDl = delta + rowbase * DINNER + d;
    const __half* pU  = u     + rowbase * DINNER + d;
    const float*  pB  = xdbl  + rowbase * XDBLW + DTRANK + n;
    const float*  pC  = pB + DSTATE;
    const float*  pZ  = xz    + rowbase * XZW + DINNER + d;

    float cdl[UNR], cuu[UNR], cBn[UNR], cCn[UNR], czz[UNR];

    auto load_grp = [&](int g, float* adl, float* auu, float* aBn,
                        float* aCn, float* azz) {
        const int l0 = g * UNR;
#pragma unroll
        for (int i = 0; i < UNR; i++) {
            adl[i] = __half2float(pDl[(size_t)(l0 + i) * DINNER]);
            auu[i] = __half2float(pU [(size_t)(l0 + i) * DINNER]);
            aBn[i] = pB[(size_t)(l0 + i) * XDBLW];
            aCn[i] = pC[(size_t)(l0 + i) * XDBLW];
        }
        if (ln0) {
#pragma unroll
            for (int i = 0; i < UNR; i++)
                azz[i] = pZ[(size_t)(l0 + i) * XZW];
        }
    };

    load_grp(0, cdl, cuu, cBn, cCn, czz);
    float h = 0.f;

    for (int g = 0; g < NGRP; g++) {
        float ndl[UNR], nuu[UNR], nBn[UNR], nCn[UNR], nzz[UNR];
        load_grp((g + 1 < NGRP) ? (g + 1) : 0, ndl, nuu, nBn, nCn, nzz);

        float dA[UNR];
#pragma unroll
        for (int i = 0; i < UNR; i++) dA[i] = __expf(cdl[i] * Aneg);

        float yp[UNR];
#pragma unroll
        for (int i = 0; i < UNR; i++) {
            h = fmaf(dA[i], h, cdl[i] * cBn[i] * cuu[i]);
            yp[i] = h * cCn[i];
        }

#pragma unroll
        for (int s = 1; s <= 8; s <<= 1) {
#pragma unroll
            for (int i = 0; i < UNR; i++)
                yp[i] += __shfl_xor_sync(0xffffffffu, yp[i], s);
        }

        if (ln0) {
            const int l0 = g * UNR;
#pragma unroll
            for (int i = 0; i < UNR; i++) {
                float y = fmaf(cuu[i], Dd, yp[i]);
                const float zz = czz[i];
                y *= zz / (1.f + __expf(-zz));
                const size_t row  = rowbase + l0 + i;
                const size_t orow = dir ? (row ^ (SEQL - 1)) : row;
                ypre[orow * DINNER + d] = __float2half_rn(y);
            }
        }

#pragma unroll
        for (int i = 0; i < UNR; i++) {
            cdl[i] = ndl[i]; cuu[i] = nuu[i];
            cBn[i] = nBn[i]; cCn[i] = nCn[i]; czz[i] = nzz[i];
        }
    }
}

// ---------------------------------------------------------------------------
// Host launch.
// ---------------------------------------------------------------------------
extern "C" void kernel_launch(void* const* d_in, const int* in_sizes, int n_in,
                              void* d_out, int out_size)
{
    const float* x = (const float*)d_in[0];
    float* out = (float*)d_out;

    const float* f_in_w    = (const float*)d_in[1];
    const float* f_conv_w  = (const float*)d_in[2];
    const float* f_conv_b  = (const float*)d_in[3];
    const float* f_xproj_w = (const float*)d_in[4];
    const float* f_dt_w    = (const float*)d_in[5];
    const float* f_dt_b    = (const float*)d_in[6];
    const float* f_Alog    = (const float*)d_in[7];
    const float* f_D       = (const float*)d_in[8];
    const float* f_out_w   = (const float*)d_in[9];
    const float* b_in_w    = (const float*)d_in[10];
    const float* b_conv_w  = (const float*)d_in[11];
    const float* b_conv_b  = (const float*)d_in[12];
    const float* b_xproj_w = (const float*)d_in[13];
    const float* b_dt_w    = (const float*)d_in[14];
    const float* b_dt_b    = (const float*)d_in[15];
    const float* b_Alog    = (const float*)d_in[16];
    const float* b_D       = (const float*)d_in[17];
    const float* b_out_w   = (const float*)d_in[18];

    // device-global fp32 targets
    float* xz0;   float* xz1;
    float* xdbl0; float* xdbl1;
    cudaGetSymbolAddress((void**)&xz0,   g_xz);
    xz1   = xz0   + (size_t)MTOT * XZW;
    cudaGetSymbolAddress((void**)&xdbl0, g_xdbl);
    xdbl1 = xdbl0 + (size_t)MTOT * XDBLW;

    cudaFuncSetAttribute(gemm_h<true,  false>,
                         cudaFuncAttributeMaxDynamicSharedMemorySize, SMEM_G);
    cudaFuncSetAttribute(gemm_h<false, true>,
                         cudaFuncAttributeMaxDynamicSharedMemorySize, SMEM_G);

    // fused init: zero out/xdbl + fp16 conversion of all GEMM operands
    init_kernel<<<dim3(160, 12), 256>>>(
        (float4*)out, (const float4*)x,
        (const float4*)f_in_w,    (const float4*)b_in_w,
        (const float4*)f_out_w,   (const float4*)b_out_w,
        (const float4*)f_xproj_w, (const float4*)b_xproj_w,
        (const float4*)f_dt_w,    (const float4*)b_dt_w);

    // in_proj: xz = x(flip dir1) @ in_w^T   [2048,3072], K=768
    gemm_h<true, false>
        <<<dim3(XZW / 128, MTOT / 128, 2), 256, SMEM_G>>>(
        HBUF_XR, HBUF_WIN, nullptr, xz0, xz1,
        XZW, DMODEL, DMODEL, XZW, XZW / 128, DMODEL);

    // depthwise conv + SiLU (fp32 in, fp16 out)
    conv_silu_kernel<<<dim3(((MTOT / 4) * (DINNER / 4) + 255) / 256, 2), 256>>>(
        f_conv_w, f_conv_b, b_conv_w, b_conv_b);

    // x_proj (split-K x8, atomic): xdbl += u_h @ xproj_w^T   [2048,80], K=1536
    gemm_h<false, true>
        <<<dim3(8, MTOT / 128, 2), 256, SMEM_G>>>(
        HBUF_UR, HBUF_WXP, nullptr, xdbl0, xdbl1,
        XDBLW, DINNER, DINNER, XDBLW, 1, DINNER / 8);

    // delta (fp16 out): softplus(dt @ dt_w^T + dt_b)  [2048,1536], K=48
    gemm_delta<<<dim3(DINNER / 128, MTOT / 128, 2), 256>>>(f_dt_b, b_dt_b);

    // selective scan (delta/u fp16, z/B/C fp32; dir1 output pre-flipped)
    scan_kernel<<<dim3((NB * DINNER) / 8, 2), 128>>>(f_Alog, f_D, b_Alog, b_D);

    // out_proj (split-K x2, atomic): out += ypre_h @ out_w^T  [2048,768], K=1536
    gemm_h<false, true>
        <<<dim3((DMODEL / 128) * 2, MTOT / 128, 2), 256, SMEM_G>>>(
        HBUF_YPRE, HBUF_WOUT, out, nullptr, nullptr,
        DMODEL, DINNER, DINNER, DMODEL, DMODEL / 128, DINNER / 2);
}